// round 3
// baseline (speedup 1.0000x reference)
#include <cuda_runtime.h>

namespace {
constexpr int S  = 8192;
constexpr int D  = 64;
constexpr int W  = 64;
constexpr int TQ = 32;            // queries per CTA
constexpr int KR = TQ + 2 * W;    // 160 key rows per CTA
constexpr int SP = 164;           // score row pitch (float4 aligned)
constexpr int NT = 128;           // 4 warps; each owns 8 query rows
constexpr int RWQ = 8;            // rows per warp
// Ks (swizzled) [KR][64] + Qs [TQ][64] + Sc [TQ][SP]   (no Vs -> 3 CTAs/SM)
constexpr int SMEM_FLOATS = KR * 64 + TQ * 64 + TQ * SP;
constexpr int SMEM_BYTES  = SMEM_FLOATS * 4;   // 70144 B
}

// ---- packed f32x2 helpers --------------------------------------------------
__device__ __forceinline__ unsigned long long ffma2(unsigned long long acc,
                                                    unsigned long long a,
                                                    unsigned long long b) {
    asm("fma.rn.f32x2 %0, %1, %2, %0;" : "+l"(acc) : "l"(a), "l"(b));
    return acc;
}
__device__ __forceinline__ unsigned long long dup2(float p) {
    unsigned long long u;
    asm("mov.b64 %0, {%1, %1};" : "=l"(u) : "f"(p));
    return u;
}
__device__ __forceinline__ float2 unpack2(unsigned long long u) {
    float2 v;
    asm("mov.b64 {%0, %1}, %2;" : "=f"(v.x), "=f"(v.y) : "l"(u));
    return v;
}

__global__ __launch_bounds__(NT, 3)
void swa_kernel(const float* __restrict__ Q,
                const float* __restrict__ K,
                const float* __restrict__ V,
                float* __restrict__ O) {
    extern __shared__ float sm[];
    float* Ks = sm;                 // KR x 64, float2-XOR-swizzled within row
    float* Qs = Ks + KR * 64;       // TQ x 64
    float* Sc = Qs + TQ * 64;       // TQ x SP  (normalized P)

    const int tile = blockIdx.x;
    const int b  = tile >> 8;
    const int qt = (tile & 255) * TQ;
    const int KB = qt - W;

    const float* kb = K + (size_t)b * S * D;
    const float* vb = V + (size_t)b * S * D;
    const float* qb = Q + (size_t)b * S * D;

    const int t = threadIdx.x;

    // ---------------- stage K (swizzled) and Q ---------------------------
    for (int idx = t; idx < KR * (D / 4); idx += NT) {
        int row = idx >> 4, c0 = idx & 15;
        int kg = KB + row;
        float4 k4 = make_float4(0.f, 0.f, 0.f, 0.f);
        if (kg >= 0 && kg < S)
            k4 = *(const float4*)(kb + (size_t)kg * D + 4 * c0);
        int x = row & 31;                       // pair (row,d2) at 2*(d2^x)
        float* krow = Ks + row * 64;
        *(float2*)(krow + 2 * ((2 * c0)     ^ x)) = make_float2(k4.x, k4.y);
        *(float2*)(krow + 2 * ((2 * c0 + 1) ^ x)) = make_float2(k4.z, k4.w);
    }
    for (int idx = t; idx < TQ * (D / 4); idx += NT) {
        int row = idx >> 4, c = (idx & 15) << 2;
        *(float4*)(Qs + row * 64 + c) =
            *(const float4*)(qb + (size_t)(qt + row) * D + c);
    }
    __syncthreads();

    const int lane = t & 31;
    const int w    = t >> 5;   // warp w: rows [8w, 8w+8)

    float p[RWQ][5];           // scores -> probabilities, register resident

    // ---------------- score GEMM (packed over d-pairs) --------------------
    {
        unsigned long long acc[RWQ][5];
        #pragma unroll
        for (int r = 0; r < RWQ; ++r)
            #pragma unroll
            for (int s = 0; s < 5; ++s) acc[r][s] = 0ull;

        const float* krow[5];
        #pragma unroll
        for (int s = 0; s < 5; ++s) krow[s] = Ks + (lane + 32 * s) * 64;

        #pragma unroll 2
        for (int d4 = 0; d4 < 16; ++d4) {
            ulonglong2 q2[RWQ];
            #pragma unroll
            for (int r = 0; r < RWQ; ++r)       // LDS.128 broadcast
                q2[r] = *(const ulonglong2*)(Qs + (RWQ * w + r) * 64 + 4 * d4);
            #pragma unroll
            for (int h = 0; h < 2; ++h) {
                int d2 = 2 * d4 + h;
                unsigned long long kk[5];
                #pragma unroll
                for (int s = 0; s < 5; ++s)     // LDS.64 conflict-free (XOR swz)
                    kk[s] = *(const unsigned long long*)(krow[s] + 2 * (d2 ^ lane));
                #pragma unroll
                for (int r = 0; r < RWQ; ++r) {
                    unsigned long long qq = h ? q2[r].y : q2[r].x;
                    #pragma unroll
                    for (int s = 0; s < 5; ++s)
                        acc[r][s] = ffma2(acc[r][s], qq, kk[s]);
                }
            }
        }
        #pragma unroll
        for (int r = 0; r < RWQ; ++r)
            #pragma unroll
            for (int s = 0; s < 5; ++s) {
                float2 v = unpack2(acc[r][s]);
                p[r][s] = (v.x + v.y) * 0.125f;
            }
    }

    // ---------------- in-register masked softmax --------------------------
    #pragma unroll
    for (int r = 0; r < RWQ; ++r) {
        const int row = RWQ * w + r;
        const int lo = max(row, -KB);
        const int hi = min(row + 2 * W, S - 1 - KB);
        float m = -1e30f;
        #pragma unroll
        for (int s = 0; s < 5; ++s) {
            int j = lane + 32 * s;
            if (j >= lo && j <= hi) m = fmaxf(m, p[r][s]);
        }
        m = fmaxf(m, __shfl_xor_sync(0xffffffffu, m, 16));
        m = fmaxf(m, __shfl_xor_sync(0xffffffffu, m, 8));
        m = fmaxf(m, __shfl_xor_sync(0xffffffffu, m, 4));
        m = fmaxf(m, __shfl_xor_sync(0xffffffffu, m, 2));
        m = fmaxf(m, __shfl_xor_sync(0xffffffffu, m, 1));
        float ssum = 0.f;
        #pragma unroll
        for (int s = 0; s < 5; ++s) {
            int j = lane + 32 * s;
            float e = (j >= lo && j <= hi) ? __expf(p[r][s] - m) : 0.f;
            ssum += e;
            p[r][s] = e;
        }
        ssum += __shfl_xor_sync(0xffffffffu, ssum, 16);
        ssum += __shfl_xor_sync(0xffffffffu, ssum, 8);
        ssum += __shfl_xor_sync(0xffffffffu, ssum, 4);
        ssum += __shfl_xor_sync(0xffffffffu, ssum, 2);
        ssum += __shfl_xor_sync(0xffffffffu, ssum, 1);
        float rinv = 1.f / ssum;
        #pragma unroll
        for (int s = 0; s < 5; ++s)             // conflict-free scalar STS
            Sc[row * SP + lane + 32 * s] = p[r][s] * rinv;
    }
    __syncthreads();

    // ---------------- AV: V straight from gmem (coalesced, L1-reused) -----
    {
        unsigned long long a[RWQ];
        #pragma unroll
        for (int r = 0; r < RWQ; ++r) a[r] = 0ull;

        const bool interior = (KB >= 0) && (KB + KR <= S);
        const float* vcol = vb + 2 * lane;

        if (interior) {
            #pragma unroll 2
            for (int j4 = 0; j4 < KR; j4 += 4) {
                float4 p4[RWQ];
                #pragma unroll
                for (int r = 0; r < RWQ; ++r)   // LDS.128 broadcast
                    p4[r] = *(const float4*)(Sc + (RWQ * w + r) * SP + j4);
                #pragma unroll
                for (int jj = 0; jj < 4; ++jj) {
                    unsigned long long v2 = *(const unsigned long long*)(
                        vcol + (size_t)(KB + j4 + jj) * D);
                    #pragma unroll
                    for (int r = 0; r < RWQ; ++r) {
                        float pp = jj == 0 ? p4[r].x : jj == 1 ? p4[r].y
                                 : jj == 2 ? p4[r].z : p4[r].w;
                        a[r] = ffma2(a[r], dup2(pp), v2);
                    }
                }
            }
        } else {
            #pragma unroll 2
            for (int j4 = 0; j4 < KR; j4 += 4) {
                float4 p4[RWQ];
                #pragma unroll
                for (int r = 0; r < RWQ; ++r)
                    p4[r] = *(const float4*)(Sc + (RWQ * w + r) * SP + j4);
                #pragma unroll
                for (int jj = 0; jj < 4; ++jj) {
                    int kg = min(max(KB + j4 + jj, 0), S - 1);  // p==0 outside
                    unsigned long long v2 = *(const unsigned long long*)(
                        vcol + (size_t)kg * D);
                    #pragma unroll
                    for (int r = 0; r < RWQ; ++r) {
                        float pp = jj == 0 ? p4[r].x : jj == 1 ? p4[r].y
                                 : jj == 2 ? p4[r].z : p4[r].w;
                        a[r] = ffma2(a[r], dup2(pp), v2);
                    }
                }
            }
        }
        #pragma unroll
        for (int r = 0; r < RWQ; ++r) {
            int qq = RWQ * w + r;
            float2 o2 = unpack2(a[r]);
            *(float2*)(O + ((size_t)b * S + qt + qq) * D + 2 * lane) = o2;
        }
    }
}

extern "C" void kernel_launch(void* const* d_in, const int* in_sizes, int n_in,
                              void* d_out, int out_size) {
    const float* q = (const float*)d_in[0];
    const float* k = (const float*)d_in[1];
    const float* v = (const float*)d_in[2];
    float* o = (float*)d_out;
    (void)n_in; (void)out_size;

    cudaFuncSetAttribute(swa_kernel,
                         cudaFuncAttributeMaxDynamicSharedMemorySize, SMEM_BYTES);
    const int B = in_sizes[0] / (S * D);
    swa_kernel<<<B * (S / TQ), NT, SMEM_BYTES>>>(q, k, v, o);
}

// round 4
// speedup vs baseline: 1.6899x; 1.6899x over previous
#include <cuda_runtime.h>

namespace {
constexpr int S  = 8192;
constexpr int D  = 64;
constexpr int W  = 64;
constexpr int TQ = 32;            // queries per CTA
constexpr int KR = TQ + 2 * W;    // 160 key rows per CTA
constexpr int SP = 164;           // P row pitch (float4 aligned)
constexpr int NT = 256;           // 8 warps; each owns 4 query rows
constexpr int RWQ = 4;            // rows per warp (R2 working point)
// Ks (swizzled) [KR][64] + Qs [TQ][64] + Sc [TQ][SP]
constexpr int SMEM_FLOATS = KR * 64 + TQ * 64 + TQ * SP;
constexpr int SMEM_BYTES  = SMEM_FLOATS * 4;   // 70144 B -> 2 CTAs/SM
}

// ---- packed f32x2 helpers --------------------------------------------------
__device__ __forceinline__ unsigned long long ffma2(unsigned long long acc,
                                                    unsigned long long a,
                                                    unsigned long long b) {
    asm("fma.rn.f32x2 %0, %1, %2, %0;" : "+l"(acc) : "l"(a), "l"(b));
    return acc;
}
__device__ __forceinline__ unsigned long long dup2(float p) {
    unsigned long long u;
    asm("mov.b64 %0, {%1, %1};" : "=l"(u) : "f"(p));
    return u;
}
__device__ __forceinline__ float2 unpack2(unsigned long long u) {
    float2 v;
    asm("mov.b64 {%0, %1}, %2;" : "=f"(v.x), "=f"(v.y) : "l"(u));
    return v;
}

__global__ __launch_bounds__(NT, 2)
void swa_kernel(const float* __restrict__ Q,
                const float* __restrict__ K,
                const float* __restrict__ V,
                float* __restrict__ O) {
    extern __shared__ float sm[];
    float* Ks = sm;                 // KR x 64, float2-XOR-swizzled within row
    float* Qs = Ks + KR * 64;       // TQ x 64
    float* Sc = Qs + TQ * 64;       // TQ x SP  (normalized P, per-warp private)

    const int tile = blockIdx.x;
    const int b  = tile >> 8;
    const int qt = (tile & 255) * TQ;
    const int KB = qt - W;

    const float* kb = K + (size_t)b * S * D;
    const float* vb = V + (size_t)b * S * D;
    const float* qb = Q + (size_t)b * S * D;

    const int t = threadIdx.x;

    // ---------------- stage K (swizzled) and Q ----------------------------
    for (int idx = t; idx < KR * (D / 4); idx += NT) {
        int row = idx >> 4, c0 = idx & 15;
        int kg = KB + row;
        float4 k4 = make_float4(0.f, 0.f, 0.f, 0.f);
        if (kg >= 0 && kg < S)
            k4 = *(const float4*)(kb + (size_t)kg * D + 4 * c0);
        int x = row & 31;                       // pair (row,d2) -> 2*(d2^x)
        float* krow = Ks + row * 64;
        *(float2*)(krow + 2 * ((2 * c0)     ^ x)) = make_float2(k4.x, k4.y);
        *(float2*)(krow + 2 * ((2 * c0 + 1) ^ x)) = make_float2(k4.z, k4.w);
    }
    for (int idx = t; idx < TQ * (D / 4); idx += NT) {
        int row = idx >> 4, c = (idx & 15) << 2;
        *(float4*)(Qs + row * 64 + c) =
            *(const float4*)(qb + (size_t)(qt + row) * D + c);
    }
    __syncthreads();

    const int lane = t & 31;
    const int w    = t >> 5;   // warp w: rows [4w, 4w+4)

    float p[RWQ][5];           // scores -> normalized probs, register resident

    // ---------------- score GEMM (packed over d-pairs) --------------------
    {
        unsigned long long acc[RWQ][5];
        #pragma unroll
        for (int r = 0; r < RWQ; ++r)
            #pragma unroll
            for (int s = 0; s < 5; ++s) acc[r][s] = 0ull;

        const float* krow[5];
        #pragma unroll
        for (int s = 0; s < 5; ++s) krow[s] = Ks + (lane + 32 * s) * 64;

        #pragma unroll 4
        for (int d4 = 0; d4 < 16; ++d4) {
            ulonglong2 q2[RWQ];
            #pragma unroll
            for (int r = 0; r < RWQ; ++r)       // LDS.128 broadcast
                q2[r] = *(const ulonglong2*)(Qs + (RWQ * w + r) * 64 + 4 * d4);
            #pragma unroll
            for (int h = 0; h < 2; ++h) {
                int d2 = 2 * d4 + h;
                unsigned long long kk[5];
                #pragma unroll
                for (int s = 0; s < 5; ++s)     // LDS.64 conflict-free (XOR swz)
                    kk[s] = *(const unsigned long long*)(krow[s] + 2 * (d2 ^ lane));
                #pragma unroll
                for (int r = 0; r < RWQ; ++r) {
                    unsigned long long qq = h ? q2[r].y : q2[r].x;
                    #pragma unroll
                    for (int s = 0; s < 5; ++s)
                        acc[r][s] = ffma2(acc[r][s], qq, kk[s]);
                }
            }
        }
        #pragma unroll
        for (int r = 0; r < RWQ; ++r)
            #pragma unroll
            for (int s = 0; s < 5; ++s) {
                float2 v = unpack2(acc[r][s]);
                p[r][s] = (v.x + v.y) * 0.125f;
            }
    }

    // ---------------- in-register masked softmax (per warp-owned rows) ----
    #pragma unroll
    for (int r = 0; r < RWQ; ++r) {
        const int row = RWQ * w + r;
        const int lo = max(row, -KB);
        const int hi = min(row + 2 * W, S - 1 - KB);
        float m = -1e30f;
        #pragma unroll
        for (int s = 0; s < 5; ++s) {
            int j = lane + 32 * s;
            if (j >= lo && j <= hi) m = fmaxf(m, p[r][s]);
        }
        m = fmaxf(m, __shfl_xor_sync(0xffffffffu, m, 16));
        m = fmaxf(m, __shfl_xor_sync(0xffffffffu, m, 8));
        m = fmaxf(m, __shfl_xor_sync(0xffffffffu, m, 4));
        m = fmaxf(m, __shfl_xor_sync(0xffffffffu, m, 2));
        m = fmaxf(m, __shfl_xor_sync(0xffffffffu, m, 1));
        float ssum = 0.f;
        #pragma unroll
        for (int s = 0; s < 5; ++s) {
            int j = lane + 32 * s;
            float e = (j >= lo && j <= hi) ? __expf(p[r][s] - m) : 0.f;
            ssum += e;
            p[r][s] = e;
        }
        ssum += __shfl_xor_sync(0xffffffffu, ssum, 16);
        ssum += __shfl_xor_sync(0xffffffffu, ssum, 8);
        ssum += __shfl_xor_sync(0xffffffffu, ssum, 4);
        ssum += __shfl_xor_sync(0xffffffffu, ssum, 2);
        ssum += __shfl_xor_sync(0xffffffffu, ssum, 1);
        float rinv = 1.f / ssum;
        #pragma unroll
        for (int s = 0; s < 5; ++s)             // conflict-free scalar STS
            Sc[row * SP + lane + 32 * s] = p[r][s] * rinv;
    }
    __syncwarp();   // intra-warp transpose only: Sc rows [4w,4w+4) are private

    // ---------------- AV: V straight from gmem (coalesced, L1-reused) -----
    {
        unsigned long long a[RWQ] = {0ull, 0ull, 0ull, 0ull};
        const bool interior = (KB >= 0) && (KB + KR <= S);
        const float* vcol = vb + 2 * lane;

        if (interior) {
            #pragma unroll 2
            for (int j4 = 0; j4 < KR; j4 += 4) {
                float4 p4[RWQ];
                #pragma unroll
                for (int r = 0; r < RWQ; ++r)   // LDS.128 broadcast
                    p4[r] = *(const float4*)(Sc + (RWQ * w + r) * SP + j4);
                #pragma unroll
                for (int jj = 0; jj < 4; ++jj) {
                    unsigned long long v2 = *(const unsigned long long*)(
                        vcol + (size_t)(KB + j4 + jj) * D);
                    #pragma unroll
                    for (int r = 0; r < RWQ; ++r) {
                        float pp = jj == 0 ? p4[r].x : jj == 1 ? p4[r].y
                                 : jj == 2 ? p4[r].z : p4[r].w;
                        a[r] = ffma2(a[r], dup2(pp), v2);
                    }
                }
            }
        } else {
            #pragma unroll 2
            for (int j4 = 0; j4 < KR; j4 += 4) {
                float4 p4[RWQ];
                #pragma unroll
                for (int r = 0; r < RWQ; ++r)
                    p4[r] = *(const float4*)(Sc + (RWQ * w + r) * SP + j4);
                #pragma unroll
                for (int jj = 0; jj < 4; ++jj) {
                    int kg = min(max(KB + j4 + jj, 0), S - 1);  // p==0 outside
                    unsigned long long v2 = *(const unsigned long long*)(
                        vcol + (size_t)kg * D);
                    #pragma unroll
                    for (int r = 0; r < RWQ; ++r) {
                        float pp = jj == 0 ? p4[r].x : jj == 1 ? p4[r].y
                                 : jj == 2 ? p4[r].z : p4[r].w;
                        a[r] = ffma2(a[r], dup2(pp), v2);
                    }
                }
            }
        }
        #pragma unroll
        for (int r = 0; r < RWQ; ++r) {
            int qq = RWQ * w + r;
            float2 o2 = unpack2(a[r]);
            *(float2*)(O + ((size_t)b * S + qt + qq) * D + 2 * lane) = o2;
        }
    }
}

extern "C" void kernel_launch(void* const* d_in, const int* in_sizes, int n_in,
                              void* d_out, int out_size) {
    const float* q = (const float*)d_in[0];
    const float* k = (const float*)d_in[1];
    const float* v = (const float*)d_in[2];
    float* o = (float*)d_out;
    (void)n_in; (void)out_size;

    cudaFuncSetAttribute(swa_kernel,
                         cudaFuncAttributeMaxDynamicSharedMemorySize, SMEM_BYTES);
    const int B = in_sizes[0] / (S * D);
    swa_kernel<<<B * (S / TQ), NT, SMEM_BYTES>>>(q, k, v, o);
}